// round 15
// baseline (speedup 1.0000x reference)
#include <cuda_runtime.h>
#include <cuda_bf16.h>
#include <cuda_fp16.h>
#include <cstdint>
#include <math.h>

// Problem constants
#define BB 2
#define CC 64
#define HH 128
#define WW 128
#define HS 64          // downsampled H=W
#define LL 4096        // HS*HS
#define EE 1024        // CC*16 (4x4 patch)
#define LSQ (4096*4096)

// ---------------- scratch (device globals; no allocation allowed) -------------
__device__ float  g_bgD[BB*LL*CC];          // [b][l][c] fp32 (for norms)
__device__ __half g_bgDH[BB*LL*CC];         // fp16 hi
__device__ __half g_bgDL[BB*LL*CC];         // fp16 lo
__device__ __half g_fgTH[BB*CC*LL];         // [b][c][p] fp16 hi
__device__ __half g_fgTL[BB*CC*LL];         // fp16 lo
__device__ float  g_sq[BB*LL];
__device__ float  g_ninv[BB*LL];
__device__ int    g_maskP[BB*LL];           // indexed by permuted a = j*64+i
__device__ __half g_colsF[(size_t)BB*LL*EE];  // cols fp16, [a][e]
__device__ float  g_bufA[(size_t)BB*LSQ];     // 134 MB
__device__ float  g_bufB[(size_t)BB*LSQ];     // 134 MB
__device__ __half g_softF[(size_t)BB*LSQ];    // softmax fp16 (67 MB)
__device__ __half g_outcolH[(size_t)BB*LL*EE]; // fp16 outcol, row pp = x*64+y

// ---------------- prep kernels -----------------------------------------------
__global__ void k_fgT(const float* __restrict__ fg) {
    int t = blockIdx.x * blockDim.x + threadIdx.x;
    if (t >= BB*CC*LL) return;
    int p = t & 4095, c = (t >> 12) & 63, b = t >> 18;
    int y = p >> 6, x = p & 63;
    float v = fg[(((size_t)b*CC + c)*HH + 2*y)*WW + 2*x];
    __half h = __float2half(v);
    size_t o = ((size_t)b*CC + c)*LL + p;
    g_fgTH[o] = h;
    g_fgTL[o] = __float2half(v - __half2float(h));
}

__global__ void k_bgD(const float* __restrict__ bg) {
    int t = blockIdx.x * blockDim.x + threadIdx.x;
    if (t >= BB*LL*CC) return;
    int c = t & 63, l = (t >> 6) & 4095, b = t >> 18;
    int i = l >> 6, j = l & 63;
    float v = bg[(((size_t)b*CC + c)*HH + 2*i)*WW + 2*j];
    size_t o = ((size_t)b*LL + l)*CC + c;
    g_bgD[o] = v;
    __half h = __float2half(v);
    g_bgDH[o] = h;
    g_bgDL[o] = __float2half(v - __half2float(h));
}

// per-location sum of squares over channels (one warp per l)
__global__ void k_sq() {
    int gid = blockIdx.x * blockDim.x + threadIdx.x;
    int gw = gid >> 5;
    int lane = gid & 31;
    if (gw >= BB*LL) return;
    const float* row = g_bgD + (size_t)gw * CC;
    float v0 = row[lane], v1 = row[lane + 32];
    float s = v0*v0 + v1*v1;
    #pragma unroll
    for (int o = 16; o; o >>= 1) s += __shfl_xor_sync(0xffffffffu, s, o);
    if (lane == 0) g_sq[gw] = s;
}

// patch norms (3x3 window of sq) and mask flags (written permuted)
__global__ void k_normmask(const float* __restrict__ mask) {
    int t = blockIdx.x * blockDim.x + threadIdx.x;
    if (t >= BB*LL) return;
    int b = t >> 12, l = t & 4095;
    int i = l >> 6, j = l & 63;
    float ss = 0.f, ms = 0.f;
    for (int di = -1; di <= 1; di++) {
        int ii = i + di; if (ii < 0 || ii >= HS) continue;
        for (int dj = -1; dj <= 1; dj++) {
            int jj = j + dj; if (jj < 0 || jj >= HS) continue;
            ss += g_sq[b*LL + ii*HS + jj];
            ms += mask[((size_t)b*HH + 2*ii)*WW + 2*jj];
        }
    }
    g_ninv[t] = 1.f / fmaxf(sqrtf(ss), 1e-3f);
    g_maskP[b*LL + j*HS + i] = (ms == 0.f) ? 1 : 0;
}

// 4x4 stride-2 patches of full-res background, rows permuted: a = j*64+i
__global__ void k_cols(const float* __restrict__ bg) {
    int t = blockIdx.x * blockDim.x + threadIdx.x;
    if (t >= BB*LL*EE) return;
    int e = t & 1023;
    int a = (t >> 10) & 4095;
    int b = t >> 22;
    int j = a >> 6, i = a & 63;
    int c = e >> 4, ki = (e >> 2) & 3, kj = e & 3;
    int Y = 2*i - 1 + ki, X = 2*j - 1 + kj;
    float v = 0.f;
    if (Y >= 0 && Y < HH && X >= 0 && X < WW)
        v = bg[(((size_t)b*CC + c)*HH + Y)*WW + X];
    g_colsF[(size_t)t] = __float2half(v);
}

// ---------------- tensor-core helpers -----------------------------------------
__device__ __forceinline__ void ldsm_x4(uint32_t* r, uint32_t addr) {
    asm volatile("ldmatrix.sync.aligned.m8n8.x4.shared.b16 {%0,%1,%2,%3}, [%4];"
        : "=r"(r[0]), "=r"(r[1]), "=r"(r[2]), "=r"(r[3]) : "r"(addr));
}
__device__ __forceinline__ void ldsm_x4_t(uint32_t* r, uint32_t addr) {
    asm volatile("ldmatrix.sync.aligned.m8n8.x4.trans.shared.b16 {%0,%1,%2,%3}, [%4];"
        : "=r"(r[0]), "=r"(r[1]), "=r"(r[2]), "=r"(r[3]) : "r"(addr));
}
__device__ __forceinline__ void mma_f16(float* c, const uint32_t* a, const uint32_t* b) {
    asm volatile(
        "mma.sync.aligned.m16n8k16.row.col.f32.f16.f16.f32 "
        "{%0,%1,%2,%3}, {%4,%5,%6,%7}, {%8,%9}, {%0,%1,%2,%3};"
        : "+f"(c[0]), "+f"(c[1]), "+f"(c[2]), "+f"(c[3])
        : "r"(a[0]), "r"(a[1]), "r"(a[2]), "r"(a[3]), "r"(b[0]), "r"(b[1]));
}
__device__ __forceinline__ void cpa16(uint32_t s, const void* g) {
    asm volatile("cp.async.cg.shared.global [%0], [%1], 16;" :: "r"(s), "l"(g));
}

// ---------------- GEMM1 (tensor): S0[l,p] = sum_c bgD[l,c]*fgT[c,p] -> bufA ---
// fp16 hi/lo both operands, 3 MMAs (ah*bh + ah*bl + al*bh). K=64 in 2 k32 steps.
__global__ __launch_bounds__(256) void k_gemm1() {
    __shared__ __half sAh[128][40], sAl[128][40];
    __shared__ __half sBh[32][136], sBl[32][136];
    int b = blockIdx.z;
    const __half* AH = g_bgDH + (size_t)b*LL*CC;
    const __half* AL = g_bgDL + (size_t)b*LL*CC;
    const __half* BH = g_fgTH + (size_t)b*CC*LL;
    const __half* BL = g_fgTL + (size_t)b*CC*LL;
    float* Cm = g_bufA + (size_t)b*LSQ;

    int m0 = blockIdx.y * 128, n0 = blockIdx.x * 128;
    int tid = threadIdx.x;
    int lane = tid & 31, warp = tid >> 5;
    int wm = warp & 1, wn = warp >> 1;
    int lr = lane & 15, lc = lane >> 4;

    float acc[4][4][4];
    #pragma unroll
    for (int mt = 0; mt < 4; mt++) {
        #pragma unroll
        for (int nt = 0; nt < 4; nt++) {
            #pragma unroll
            for (int q = 0; q < 4; q++) acc[mt][nt][q] = 0.f;
        }
    }

    uint32_t bAh = (uint32_t)__cvta_generic_to_shared(&sAh[0][0]);
    uint32_t bAl = (uint32_t)__cvta_generic_to_shared(&sAl[0][0]);
    uint32_t bBh = (uint32_t)__cvta_generic_to_shared(&sBh[0][0]);
    uint32_t bBl = (uint32_t)__cvta_generic_to_shared(&sBl[0][0]);

    for (int k0 = 0; k0 < 64; k0 += 32) {
        __syncthreads();
        #pragma unroll
        for (int i = 0; i < 2; i++) {
            int cid = tid + i*256;
            int m = cid >> 2, kc = (cid & 3) * 8;
            *(uint4*)&sAh[m][kc] = *(const uint4*)(AH + (size_t)(m0+m)*CC + k0 + kc);
            *(uint4*)&sAl[m][kc] = *(const uint4*)(AL + (size_t)(m0+m)*CC + k0 + kc);
            int kb = cid >> 4, nc = (cid & 15) * 8;
            *(uint4*)&sBh[kb][nc] = *(const uint4*)(BH + (size_t)(k0+kb)*LL + n0 + nc);
            *(uint4*)&sBl[kb][nc] = *(const uint4*)(BL + (size_t)(k0+kb)*LL + n0 + nc);
        }
        __syncthreads();

        #pragma unroll
        for (int kk = 0; kk < 32; kk += 16) {
            uint32_t ah[4][4], al[4][4], bh[4][2], bl[4][2];
            #pragma unroll
            for (int mt = 0; mt < 4; mt++) {
                uint32_t offa = (uint32_t)((wm*64 + mt*16 + lr) * 40 + kk + lc*8) * 2u;
                ldsm_x4(ah[mt], bAh + offa);
                ldsm_x4(al[mt], bAl + offa);
            }
            #pragma unroll
            for (int ntp = 0; ntp < 2; ntp++) {
                uint32_t offb = (uint32_t)((kk + lr) * 136 + wn*32 + ntp*16 + lc*8) * 2u;
                uint32_t rh[4], rl[4];
                ldsm_x4_t(rh, bBh + offb);
                ldsm_x4_t(rl, bBl + offb);
                bh[ntp*2][0] = rh[0]; bh[ntp*2][1] = rh[1];
                bh[ntp*2+1][0] = rh[2]; bh[ntp*2+1][1] = rh[3];
                bl[ntp*2][0] = rl[0]; bl[ntp*2][1] = rl[1];
                bl[ntp*2+1][0] = rl[2]; bl[ntp*2+1][1] = rl[3];
            }
            #pragma unroll
            for (int mt = 0; mt < 4; mt++) {
                #pragma unroll
                for (int nt = 0; nt < 4; nt++) {
                    mma_f16(acc[mt][nt], ah[mt], bh[nt]);
                    mma_f16(acc[mt][nt], ah[mt], bl[nt]);
                    mma_f16(acc[mt][nt], al[mt], bh[nt]);
                }
            }
        }
    }

    int g = lane >> 2, tig = lane & 3;
    #pragma unroll
    for (int mt = 0; mt < 4; mt++) {
        int row0 = m0 + wm*64 + mt*16 + g;
        #pragma unroll
        for (int nt = 0; nt < 4; nt++) {
            int col = n0 + wn*32 + nt*8 + tig*2;
            *(float2*)(Cm + (size_t)row0*LL + col)     = make_float2(acc[mt][nt][0], acc[mt][nt][1]);
            *(float2*)(Cm + (size_t)(row0+8)*LL + col) = make_float2(acc[mt][nt][2], acc[mt][nt][3]);
        }
    }
}

// ---------------- fused 27-tap + permutation: bufA -> bufB (permuted) ---------
// 4-outputs-per-thread, 15-row independent tap loads (R14 form).
__global__ void k_diagp() {
    __shared__ float tile[32][33];
    int z = blockIdx.z;
    int b = z >> 12;
    int jy = z & 4095;
    int j = jy >> 6, y = jy & 63;
    const float* S = g_bufA + (size_t)b*LSQ;
    float* D = g_bufB + (size_t)b*LSQ;
    int i0 = blockIdx.x * 32, x0 = blockIdx.y * 32;

    int tx = threadIdx.x;    // 0..7
    int ty = threadIdx.y;    // 0..31
    int i = i0 + ty;
    int xb = x0 + tx*4;
    int l = i*64 + j;
    int p = y*64 + xb;

    float ts[5][4];
    #pragma unroll
    for (int s = 0; s < 5; s++) {
        #pragma unroll
        for (int t = 0; t < 4; t++) ts[s][t] = 0.f;
    }
    #pragma unroll
    for (int s = -2; s <= 2; s++) {
        #pragma unroll
        for (int di = -1; di <= 1; di++) {
            int dd = s + 64*di;
            int l2 = l + dd;
            if (l2 < 0 || l2 >= LL) continue;
            const float* row = S + (size_t)l2*LL;
            int pb = p + dd;
            #pragma unroll
            for (int t = 0; t < 4; t++) {
                int p2 = pb + t;
                if (p2 >= 0 && p2 < LL) ts[s+2][t] += row[p2];
            }
        }
    }

    float out[4] = {0.f, 0.f, 0.f, 0.f};
    #pragma unroll
    for (int d = -1; d <= 1; d++) {
        int lcn = l + d;
        if (lcn < 0 || lcn >= LL) continue;
        float nv = g_ninv[b*LL + lcn];
        int jc = lcn & 63;
        #pragma unroll
        for (int t = 0; t < 4; t++) {
            int pcn = p + t + d;
            if (pcn < 0 || pcn >= LL) continue;
            int xc = pcn & 63;
            float inner = 0.f;
            #pragma unroll
            for (int dj = -1; dj <= 1; dj++) {
                if (jc + dj < 0 || jc + dj > 63 || xc + dj < 0 || xc + dj > 63) continue;
                inner += ts[d + dj + 2][t];
            }
            out[t] += inner * nv;
        }
    }

    #pragma unroll
    for (int t = 0; t < 4; t++) tile[ty][tx*4 + t] = out[t];
    __syncthreads();

    int wtid = tx + ty*8;
    int il = wtid & 31;
    #pragma unroll
    for (int k = 0; k < 4; k++) {
        int xl = (wtid >> 5) + k*8;
        D[(size_t)((x0 + xl)*64 + y)*LL + j*64 + i0 + il] = tile[il][xl];
    }
}

// ---------------- fuse #2 + mask + softmax over u: bufB -> softF (fp16) -------
__global__ __launch_bounds__(256) void k_softmax() {
    __shared__ float srow[4096];
    __shared__ float sred[8];
    int v = blockIdx.x & 4095;
    int b = blockIdx.x >> 12;
    const float* S = g_bufB + (size_t)b*LSQ;
    __half* DH = g_softF + (size_t)b*LSQ;
    int tid = threadIdx.x;
    int lane = tid & 31, wid = tid >> 5;

    float lmax = -1e30f;
    for (int u = tid; u < 4096; u += 256) {
        float acc = S[(size_t)v*LL + u];
        if (v > 0    && u > 0)    acc += S[(size_t)(v-1)*LL + u - 1];
        if (v < 4095 && u < 4095) acc += S[(size_t)(v+1)*LL + u + 1];
        float val = g_maskP[b*LL + u] ? -1000.f : acc;
        val *= 10.f;
        srow[u] = val;
        lmax = fmaxf(lmax, val);
    }
    #pragma unroll
    for (int o = 16; o; o >>= 1) lmax = fmaxf(lmax, __shfl_xor_sync(0xffffffffu, lmax, o));
    if (lane == 0) sred[wid] = lmax;
    __syncthreads();
    if (tid == 0) {
        float m = sred[0];
        #pragma unroll
        for (int w = 1; w < 8; w++) m = fmaxf(m, sred[w]);
        sred[0] = m;
    }
    __syncthreads();
    float gmax = sred[0];
    __syncthreads();

    float lsum = 0.f;
    for (int u = tid; u < 4096; u += 256) {
        float e = __expf(srow[u] - gmax);
        srow[u] = e;
        lsum += e;
    }
    #pragma unroll
    for (int o = 16; o; o >>= 1) lsum += __shfl_xor_sync(0xffffffffu, lsum, o);
    if (lane == 0) sred[wid] = lsum;
    __syncthreads();
    if (tid == 0) {
        float s2 = 0.f;
        #pragma unroll
        for (int w = 0; w < 8; w++) s2 += sred[w];
        sred[0] = s2;
    }
    __syncthreads();
    float inv = 1.f / sred[0];
    for (int u = tid; u < 4096; u += 256)
        DH[(size_t)v*LL + u] = __float2half(srow[u] * inv);
}

// ---------------- GEMM2 (3-stage ring, wait_group 1): OutCol = soft @ cols ----
// A = single fp16 softmax, B = single fp16 cols. 1 MMA per k16. fp16 epilogue.
// 3 x 16KB static smem. Loop: wait(stage i ready, allow newest in flight) ->
// sync -> issue stage i+2 -> compute stage i. Stage-i loads were issued two
// iterations back, so ~2 compute blocks cover the load latency.
#define G2_STG 16384u   // per-stage bytes: A 8192 + B 8192
__global__ __launch_bounds__(256) void k_gemm2() {
    __shared__ char smem[3*G2_STG];   // 49152 B
    uint32_t sb = (uint32_t)__cvta_generic_to_shared(smem);

    int b = blockIdx.z;
    const __half* Af = g_softF + (size_t)b*LSQ;
    const __half* Bf = g_colsF + (size_t)b*LL*EE;
    __half* Cm = g_outcolH + (size_t)b*LL*EE;

    int m0 = blockIdx.y * 128, n0 = blockIdx.x * 128;
    int tid = threadIdx.x;
    int lane = tid & 31, warp = tid >> 5;
    int wm = warp & 1, wn = warp >> 1;
    int lr = lane & 15, lc = lane >> 4;

    float acc[4][4][4];
    #pragma unroll
    for (int mt = 0; mt < 4; mt++) {
        #pragma unroll
        for (int nt = 0; nt < 4; nt++) {
            #pragma unroll
            for (int q = 0; q < 4; q++) acc[mt][nt][q] = 0.f;
        }
    }

    // per-thread load slots (2 chunks per matrix per thread, 512 chunks each)
    int c0 = tid, c1 = tid + 256;
    int mA0 = c0 >> 2, cA0 = c0 & 3;
    int mA1 = c1 >> 2, cA1 = c1 & 3;
    uint32_t dA0 = (uint32_t)(mA0*64 + (cA0 ^ ((mA0>>1)&3))*16);
    uint32_t dA1 = (uint32_t)(mA1*64 + (cA1 ^ ((mA1>>1)&3))*16);
    int kB0 = c0 >> 4, cB0 = c0 & 15;
    int kB1 = c1 >> 4, cB1 = c1 & 15;
    uint32_t dB0 = (uint32_t)(kB0*256 + (cB0 ^ (kB0&7))*16);
    uint32_t dB1 = (uint32_t)(kB1*256 + (cB1 ^ (kB1&7))*16);

    const int STEPS = LL / 32;   // 128

    // prologue: issue stages 0 and 1 (two committed groups)
    #pragma unroll
    for (int pi = 0; pi < 2; pi++) {
        int k0 = pi * 32;
        uint32_t s = sb + (uint32_t)(pi * (int)G2_STG);
        cpa16(s + dA0,          Af + (size_t)(m0+mA0)*LL + k0 + cA0*8);
        cpa16(s + dA1,          Af + (size_t)(m0+mA1)*LL + k0 + cA1*8);
        cpa16(s + 8192u + dB0,  Bf + (size_t)(k0+kB0)*EE + n0 + cB0*8);
        cpa16(s + 8192u + dB1,  Bf + (size_t)(k0+kB1)*EE + n0 + cB1*8);
        asm volatile("cp.async.commit_group;");
    }

    int stg = 0;   // stage buffer index for iteration i
    for (int i = 0; i < STEPS; i++) {
        // groups newer than stage i's: exactly one (stage i+1) unless i is last
        if (i + 1 < STEPS) {
            asm volatile("cp.async.wait_group 1;");
        } else {
            asm volatile("cp.async.wait_group 0;");
        }
        __syncthreads();

        // issue loads for stage i+2 into buffer (stg+2)%3 (last read in iter i-1)
        if (i + 2 < STEPS) {
            int k0 = (i + 2) * 32;
            int s2 = stg + 2; if (s2 >= 3) s2 -= 3;
            uint32_t s = sb + (uint32_t)(s2 * (int)G2_STG);
            cpa16(s + dA0,          Af + (size_t)(m0+mA0)*LL + k0 + cA0*8);
            cpa16(s + dA1,          Af + (size_t)(m0+mA1)*LL + k0 + cA1*8);
            cpa16(s + 8192u + dB0,  Bf + (size_t)(k0+kB0)*EE + n0 + cB0*8);
            cpa16(s + 8192u + dB1,  Bf + (size_t)(k0+kB1)*EE + n0 + cB1*8);
            asm volatile("cp.async.commit_group;");
        }

        uint32_t st = sb + (uint32_t)(stg * (int)G2_STG);
        #pragma unroll
        for (int kk = 0; kk < 32; kk += 16) {
            uint32_t af[4][4], bfr[4][2];
            #pragma unroll
            for (int mt = 0; mt < 4; mt++) {
                int row = wm*64 + mt*16 + lr;
                int ca = (kk >> 3) + lc;
                uint32_t offa = (uint32_t)(row*64 + ((ca ^ ((row>>1)&3)))*16);
                ldsm_x4(af[mt], st + offa);
            }
            #pragma unroll
            for (int ntp = 0; ntp < 2; ntp++) {
                int krow = kk + lr;
                int cb = wn*4 + ntp*2 + lc;
                uint32_t offb = 8192u + (uint32_t)(krow*256 + ((cb ^ (krow&7)))*16);
                uint32_t rh[4];
                ldsm_x4_t(rh, st + offb);
                bfr[ntp*2][0] = rh[0]; bfr[ntp*2][1] = rh[1];
                bfr[ntp*2+1][0] = rh[2]; bfr[ntp*2+1][1] = rh[3];
            }
            #pragma unroll
            for (int mt = 0; mt < 4; mt++) {
                #pragma unroll
                for (int nt = 0; nt < 4; nt++) {
                    mma_f16(acc[mt][nt], af[mt], bfr[nt]);
                }
            }
        }
        __syncthreads();
        if (++stg == 3) stg = 0;
    }

    int g = lane >> 2, tig = lane & 3;
    #pragma unroll
    for (int mt = 0; mt < 4; mt++) {
        int row0 = m0 + wm*64 + mt*16 + g;
        #pragma unroll
        for (int nt = 0; nt < 4; nt++) {
            int col = n0 + wn*32 + nt*8 + tig*2;
            __half2 v0 = __floats2half2_rn(acc[mt][nt][0], acc[mt][nt][1]);
            __half2 v1 = __floats2half2_rn(acc[mt][nt][2], acc[mt][nt][3]);
            *(__half2*)(Cm + (size_t)row0*EE + col)     = v0;
            *(__half2*)(Cm + (size_t)(row0+8)*EE + col) = v1;
        }
    }
}

// ---------------- overlap-add (transposed conv gather, fp16 in) ---------------
__global__ void k_overlap(float* __restrict__ out) {
    int idx = blockIdx.x * blockDim.x + threadIdx.x;
    if (idx >= BB*CC*HH*WW) return;
    int X = idx & 127, Y = (idx >> 7) & 127, c = (idx >> 14) & 63, b = idx >> 20;
    float acc = 0.f;
    int y0 = (Y + 1) >> 1;
    int x0 = (X + 1) >> 1;
    #pragma unroll
    for (int dy = 0; dy < 2; dy++) {
        int yc = y0 - dy;
        if (yc < 0 || yc >= 64) continue;
        int ki = Y + 1 - 2*yc;
        if (ki < 0 || ki > 3) continue;
        #pragma unroll
        for (int dx = 0; dx < 2; dx++) {
            int xc = x0 - dx;
            if (xc < 0 || xc >= 64) continue;
            int kj = X + 1 - 2*xc;
            if (kj < 0 || kj > 3) continue;
            acc += __half2float(
                g_outcolH[((size_t)b*LL + xc*64 + yc)*EE + c*16 + ki*4 + kj]);
        }
    }
    out[idx] = acc;
}

// ---------------- launch -------------------------------------------------------
extern "C" void kernel_launch(void* const* d_in, const int* in_sizes, int n_in,
                              void* d_out, int out_size) {
    const float* fg   = (const float*)d_in[0];
    const float* bg   = (const float*)d_in[1];
    const float* mask = (const float*)d_in[2];
    float* out = (float*)d_out;

    k_fgT<<<2048, 256>>>(fg);
    k_bgD<<<2048, 256>>>(bg);
    k_sq<<<1024, 256>>>();
    k_normmask<<<32, 256>>>(mask);
    k_cols<<<32768, 256>>>(bg);

    k_gemm1<<<dim3(32, 32, BB), 256>>>();                 // tensor -> bufA
    k_diagp<<<dim3(2, 2, BB*4096), dim3(8, 32)>>>();      // bufA -> bufB (4-wide taps)
    k_softmax<<<BB*4096, 256>>>();                        // bufB -> softF (fp16)
    k_gemm2<<<dim3(8, 32, BB), 256>>>();                  // 3-stage ring -> outcolH
    k_overlap<<<8192, 256>>>(out);
}

// round 16
// speedup vs baseline: 1.4139x; 1.4139x over previous
#include <cuda_runtime.h>
#include <cuda_bf16.h>
#include <cuda_fp16.h>
#include <cstdint>
#include <math.h>

// Problem constants
#define BB 2
#define CC 64
#define HH 128
#define WW 128
#define HS 64          // downsampled H=W
#define LL 4096        // HS*HS
#define EE 1024        // CC*16 (4x4 patch)
#define LSQ (4096*4096)
#define CAP 256        // max kept softmax entries per row

// ---------------- scratch (device globals; no allocation allowed) -------------
__device__ float  g_bgD[BB*LL*CC];          // [b][l][c] fp32 (for norms)
__device__ __half g_bgDH[BB*LL*CC];         // fp16 hi
__device__ __half g_bgDL[BB*LL*CC];         // fp16 lo
__device__ __half g_fgTH[BB*CC*LL];         // [b][c][p] fp16 hi
__device__ __half g_fgTL[BB*CC*LL];         // fp16 lo
__device__ float  g_sq[BB*LL];
__device__ float  g_ninv[BB*LL];
__device__ int    g_maskP[BB*LL];           // indexed by permuted a = j*64+i
__device__ __half g_colsF[(size_t)BB*LL*EE];  // cols fp16, [a][e]
__device__ float  g_bufA[(size_t)BB*LSQ];     // 134 MB
__device__ float  g_bufB[(size_t)BB*LSQ];     // 134 MB
__device__ int    g_scnt[BB*LL];              // sparse row counts
__device__ int    g_sidx[(size_t)BB*LL*CAP];  // sparse col indices (8.4 MB)
__device__ float  g_sw  [(size_t)BB*LL*CAP];  // sparse weights (8.4 MB)
__device__ __half g_outcolH[(size_t)BB*LL*EE]; // fp16 outcol, row pp = x*64+y

// ---------------- prep kernels -----------------------------------------------
__global__ void k_fgT(const float* __restrict__ fg) {
    int t = blockIdx.x * blockDim.x + threadIdx.x;
    if (t >= BB*CC*LL) return;
    int p = t & 4095, c = (t >> 12) & 63, b = t >> 18;
    int y = p >> 6, x = p & 63;
    float v = fg[(((size_t)b*CC + c)*HH + 2*y)*WW + 2*x];
    __half h = __float2half(v);
    size_t o = ((size_t)b*CC + c)*LL + p;
    g_fgTH[o] = h;
    g_fgTL[o] = __float2half(v - __half2float(h));
}

__global__ void k_bgD(const float* __restrict__ bg) {
    int t = blockIdx.x * blockDim.x + threadIdx.x;
    if (t >= BB*LL*CC) return;
    int c = t & 63, l = (t >> 6) & 4095, b = t >> 18;
    int i = l >> 6, j = l & 63;
    float v = bg[(((size_t)b*CC + c)*HH + 2*i)*WW + 2*j];
    size_t o = ((size_t)b*LL + l)*CC + c;
    g_bgD[o] = v;
    __half h = __float2half(v);
    g_bgDH[o] = h;
    g_bgDL[o] = __float2half(v - __half2float(h));
}

// per-location sum of squares over channels (one warp per l)
__global__ void k_sq() {
    int gid = blockIdx.x * blockDim.x + threadIdx.x;
    int gw = gid >> 5;
    int lane = gid & 31;
    if (gw >= BB*LL) return;
    const float* row = g_bgD + (size_t)gw * CC;
    float v0 = row[lane], v1 = row[lane + 32];
    float s = v0*v0 + v1*v1;
    #pragma unroll
    for (int o = 16; o; o >>= 1) s += __shfl_xor_sync(0xffffffffu, s, o);
    if (lane == 0) g_sq[gw] = s;
}

// patch norms (3x3 window of sq) and mask flags (written permuted)
__global__ void k_normmask(const float* __restrict__ mask) {
    int t = blockIdx.x * blockDim.x + threadIdx.x;
    if (t >= BB*LL) return;
    int b = t >> 12, l = t & 4095;
    int i = l >> 6, j = l & 63;
    float ss = 0.f, ms = 0.f;
    for (int di = -1; di <= 1; di++) {
        int ii = i + di; if (ii < 0 || ii >= HS) continue;
        for (int dj = -1; dj <= 1; dj++) {
            int jj = j + dj; if (jj < 0 || jj >= HS) continue;
            ss += g_sq[b*LL + ii*HS + jj];
            ms += mask[((size_t)b*HH + 2*ii)*WW + 2*jj];
        }
    }
    g_ninv[t] = 1.f / fmaxf(sqrtf(ss), 1e-3f);
    g_maskP[b*LL + j*HS + i] = (ms == 0.f) ? 1 : 0;
}

// 4x4 stride-2 patches of full-res background, rows permuted: a = j*64+i
__global__ void k_cols(const float* __restrict__ bg) {
    int t = blockIdx.x * blockDim.x + threadIdx.x;
    if (t >= BB*LL*EE) return;
    int e = t & 1023;
    int a = (t >> 10) & 4095;
    int b = t >> 22;
    int j = a >> 6, i = a & 63;
    int c = e >> 4, ki = (e >> 2) & 3, kj = e & 3;
    int Y = 2*i - 1 + ki, X = 2*j - 1 + kj;
    float v = 0.f;
    if (Y >= 0 && Y < HH && X >= 0 && X < WW)
        v = bg[(((size_t)b*CC + c)*HH + Y)*WW + X];
    g_colsF[(size_t)t] = __float2half(v);
}

// ---------------- tensor-core helpers -----------------------------------------
__device__ __forceinline__ void ldsm_x4(uint32_t* r, uint32_t addr) {
    asm volatile("ldmatrix.sync.aligned.m8n8.x4.shared.b16 {%0,%1,%2,%3}, [%4];"
        : "=r"(r[0]), "=r"(r[1]), "=r"(r[2]), "=r"(r[3]) : "r"(addr));
}
__device__ __forceinline__ void ldsm_x4_t(uint32_t* r, uint32_t addr) {
    asm volatile("ldmatrix.sync.aligned.m8n8.x4.trans.shared.b16 {%0,%1,%2,%3}, [%4];"
        : "=r"(r[0]), "=r"(r[1]), "=r"(r[2]), "=r"(r[3]) : "r"(addr));
}
__device__ __forceinline__ void mma_f16(float* c, const uint32_t* a, const uint32_t* b) {
    asm volatile(
        "mma.sync.aligned.m16n8k16.row.col.f32.f16.f16.f32 "
        "{%0,%1,%2,%3}, {%4,%5,%6,%7}, {%8,%9}, {%0,%1,%2,%3};"
        : "+f"(c[0]), "+f"(c[1]), "+f"(c[2]), "+f"(c[3])
        : "r"(a[0]), "r"(a[1]), "r"(a[2]), "r"(a[3]), "r"(b[0]), "r"(b[1]));
}

// ---------------- GEMM1 (tensor): S0[l,p] = sum_c bgD[l,c]*fgT[c,p] -> bufA ---
// fp16 hi/lo both operands, 3 MMAs (ah*bh + ah*bl + al*bh). K=64 in 2 k32 steps.
__global__ __launch_bounds__(256) void k_gemm1() {
    __shared__ __half sAh[128][40], sAl[128][40];
    __shared__ __half sBh[32][136], sBl[32][136];
    int b = blockIdx.z;
    const __half* AH = g_bgDH + (size_t)b*LL*CC;
    const __half* AL = g_bgDL + (size_t)b*LL*CC;
    const __half* BH = g_fgTH + (size_t)b*CC*LL;
    const __half* BL = g_fgTL + (size_t)b*CC*LL;
    float* Cm = g_bufA + (size_t)b*LSQ;

    int m0 = blockIdx.y * 128, n0 = blockIdx.x * 128;
    int tid = threadIdx.x;
    int lane = tid & 31, warp = tid >> 5;
    int wm = warp & 1, wn = warp >> 1;
    int lr = lane & 15, lc = lane >> 4;

    float acc[4][4][4];
    #pragma unroll
    for (int mt = 0; mt < 4; mt++) {
        #pragma unroll
        for (int nt = 0; nt < 4; nt++) {
            #pragma unroll
            for (int q = 0; q < 4; q++) acc[mt][nt][q] = 0.f;
        }
    }

    uint32_t bAh = (uint32_t)__cvta_generic_to_shared(&sAh[0][0]);
    uint32_t bAl = (uint32_t)__cvta_generic_to_shared(&sAl[0][0]);
    uint32_t bBh = (uint32_t)__cvta_generic_to_shared(&sBh[0][0]);
    uint32_t bBl = (uint32_t)__cvta_generic_to_shared(&sBl[0][0]);

    for (int k0 = 0; k0 < 64; k0 += 32) {
        __syncthreads();
        #pragma unroll
        for (int i = 0; i < 2; i++) {
            int cid = tid + i*256;
            int m = cid >> 2, kc = (cid & 3) * 8;
            *(uint4*)&sAh[m][kc] = *(const uint4*)(AH + (size_t)(m0+m)*CC + k0 + kc);
            *(uint4*)&sAl[m][kc] = *(const uint4*)(AL + (size_t)(m0+m)*CC + k0 + kc);
            int kb = cid >> 4, nc = (cid & 15) * 8;
            *(uint4*)&sBh[kb][nc] = *(const uint4*)(BH + (size_t)(k0+kb)*LL + n0 + nc);
            *(uint4*)&sBl[kb][nc] = *(const uint4*)(BL + (size_t)(k0+kb)*LL + n0 + nc);
        }
        __syncthreads();

        #pragma unroll
        for (int kk = 0; kk < 32; kk += 16) {
            uint32_t ah[4][4], al[4][4], bh[4][2], bl[4][2];
            #pragma unroll
            for (int mt = 0; mt < 4; mt++) {
                uint32_t offa = (uint32_t)((wm*64 + mt*16 + lr) * 40 + kk + lc*8) * 2u;
                ldsm_x4(ah[mt], bAh + offa);
                ldsm_x4(al[mt], bAl + offa);
            }
            #pragma unroll
            for (int ntp = 0; ntp < 2; ntp++) {
                uint32_t offb = (uint32_t)((kk + lr) * 136 + wn*32 + ntp*16 + lc*8) * 2u;
                uint32_t rh[4], rl[4];
                ldsm_x4_t(rh, bBh + offb);
                ldsm_x4_t(rl, bBl + offb);
                bh[ntp*2][0] = rh[0]; bh[ntp*2][1] = rh[1];
                bh[ntp*2+1][0] = rh[2]; bh[ntp*2+1][1] = rh[3];
                bl[ntp*2][0] = rl[0]; bl[ntp*2][1] = rl[1];
                bl[ntp*2+1][0] = rl[2]; bl[ntp*2+1][1] = rl[3];
            }
            #pragma unroll
            for (int mt = 0; mt < 4; mt++) {
                #pragma unroll
                for (int nt = 0; nt < 4; nt++) {
                    mma_f16(acc[mt][nt], ah[mt], bh[nt]);
                    mma_f16(acc[mt][nt], ah[mt], bl[nt]);
                    mma_f16(acc[mt][nt], al[mt], bh[nt]);
                }
            }
        }
    }

    int g = lane >> 2, tig = lane & 3;
    #pragma unroll
    for (int mt = 0; mt < 4; mt++) {
        int row0 = m0 + wm*64 + mt*16 + g;
        #pragma unroll
        for (int nt = 0; nt < 4; nt++) {
            int col = n0 + wn*32 + nt*8 + tig*2;
            *(float2*)(Cm + (size_t)row0*LL + col)     = make_float2(acc[mt][nt][0], acc[mt][nt][1]);
            *(float2*)(Cm + (size_t)(row0+8)*LL + col) = make_float2(acc[mt][nt][2], acc[mt][nt][3]);
        }
    }
}

// ---------------- fused 27-tap + permutation: bufA -> bufB (permuted) ---------
// 4-outputs-per-thread, 15-row independent tap loads (R14 form).
__global__ void k_diagp() {
    __shared__ float tile[32][33];
    int z = blockIdx.z;
    int b = z >> 12;
    int jy = z & 4095;
    int j = jy >> 6, y = jy & 63;
    const float* S = g_bufA + (size_t)b*LSQ;
    float* D = g_bufB + (size_t)b*LSQ;
    int i0 = blockIdx.x * 32, x0 = blockIdx.y * 32;

    int tx = threadIdx.x;    // 0..7
    int ty = threadIdx.y;    // 0..31
    int i = i0 + ty;
    int xb = x0 + tx*4;
    int l = i*64 + j;
    int p = y*64 + xb;

    float ts[5][4];
    #pragma unroll
    for (int s = 0; s < 5; s++) {
        #pragma unroll
        for (int t = 0; t < 4; t++) ts[s][t] = 0.f;
    }
    #pragma unroll
    for (int s = -2; s <= 2; s++) {
        #pragma unroll
        for (int di = -1; di <= 1; di++) {
            int dd = s + 64*di;
            int l2 = l + dd;
            if (l2 < 0 || l2 >= LL) continue;
            const float* row = S + (size_t)l2*LL;
            int pb = p + dd;
            #pragma unroll
            for (int t = 0; t < 4; t++) {
                int p2 = pb + t;
                if (p2 >= 0 && p2 < LL) ts[s+2][t] += row[p2];
            }
        }
    }

    float out[4] = {0.f, 0.f, 0.f, 0.f};
    #pragma unroll
    for (int d = -1; d <= 1; d++) {
        int lcn = l + d;
        if (lcn < 0 || lcn >= LL) continue;
        float nv = g_ninv[b*LL + lcn];
        int jc = lcn & 63;
        #pragma unroll
        for (int t = 0; t < 4; t++) {
            int pcn = p + t + d;
            if (pcn < 0 || pcn >= LL) continue;
            int xc = pcn & 63;
            float inner = 0.f;
            #pragma unroll
            for (int dj = -1; dj <= 1; dj++) {
                if (jc + dj < 0 || jc + dj > 63 || xc + dj < 0 || xc + dj > 63) continue;
                inner += ts[d + dj + 2][t];
            }
            out[t] += inner * nv;
        }
    }

    #pragma unroll
    for (int t = 0; t < 4; t++) tile[ty][tx*4 + t] = out[t];
    __syncthreads();

    int wtid = tx + ty*8;
    int il = wtid & 31;
    #pragma unroll
    for (int k = 0; k < 4; k++) {
        int xl = (wtid >> 5) + k*8;
        D[(size_t)((x0 + xl)*64 + y)*LL + j*64 + i0 + il] = tile[il][xl];
    }
}

// ---------------- fuse #2 + mask + softmax -> SPARSE lists --------------------
// Keeps entries with val > gmax - 18 (dropped mass <= 4096*e^-18 = 6.2e-5,
// unconditional). Exact full-row normalization. Deterministic two-pass
// compaction (warp scans, no atomics). Cap CAP entries (clamp, prob ~0).
__global__ __launch_bounds__(256) void k_softsp() {
    __shared__ float srow[4096];
    __shared__ float sred[8];
    __shared__ int   swtot[8];
    __shared__ int   swpre[9];
    int v = blockIdx.x & 4095;
    int b = blockIdx.x >> 12;
    const float* S = g_bufB + (size_t)b*LSQ;
    int rowg = b*LL + v;
    int tid = threadIdx.x;
    int lane = tid & 31, wid = tid >> 5;

    float lmax = -1e30f;
    for (int u = tid; u < 4096; u += 256) {
        float acc = S[(size_t)v*LL + u];
        if (v > 0    && u > 0)    acc += S[(size_t)(v-1)*LL + u - 1];
        if (v < 4095 && u < 4095) acc += S[(size_t)(v+1)*LL + u + 1];
        float val = g_maskP[b*LL + u] ? -1000.f : acc;
        val *= 10.f;
        srow[u] = val;
        lmax = fmaxf(lmax, val);
    }
    #pragma unroll
    for (int o = 16; o; o >>= 1) lmax = fmaxf(lmax, __shfl_xor_sync(0xffffffffu, lmax, o));
    if (lane == 0) sred[wid] = lmax;
    __syncthreads();
    if (tid == 0) {
        float m = sred[0];
        #pragma unroll
        for (int w = 1; w < 8; w++) m = fmaxf(m, sred[w]);
        sred[0] = m;
    }
    __syncthreads();
    float gmax = sred[0];
    __syncthreads();

    // exact denominator over all entries
    float lsum = 0.f;
    for (int u = tid; u < 4096; u += 256)
        lsum += __expf(srow[u] - gmax);
    #pragma unroll
    for (int o = 16; o; o >>= 1) lsum += __shfl_xor_sync(0xffffffffu, lsum, o);
    if (lane == 0) sred[wid] = lsum;
    __syncthreads();
    if (tid == 0) {
        float s2 = 0.f;
        #pragma unroll
        for (int w = 0; w < 8; w++) s2 += sred[w];
        sred[0] = s2;
    }
    __syncthreads();
    float inv = 1.f / sred[0];

    // sparse compaction: threshold gmax - 18
    float T = gmax - 18.f;
    int cnt = 0;
    for (int u = tid; u < 4096; u += 256)
        if (srow[u] > T) cnt++;
    int incl = cnt;
    #pragma unroll
    for (int o = 1; o < 32; o <<= 1) {
        int n = __shfl_up_sync(0xffffffffu, incl, o);
        if (lane >= o) incl += n;
    }
    if (lane == 31) swtot[wid] = incl;
    __syncthreads();
    if (tid == 0) {
        int s = 0;
        #pragma unroll
        for (int w = 0; w < 8; w++) { swpre[w] = s; s += swtot[w]; }
        swpre[8] = s;
    }
    __syncthreads();
    int pos = swpre[wid] + incl - cnt;
    int total = swpre[8];

    int*   idx = g_sidx + (size_t)rowg * CAP;
    float* wts = g_sw   + (size_t)rowg * CAP;
    for (int u = tid; u < 4096; u += 256) {
        if (srow[u] > T) {
            if (pos < CAP) {
                idx[pos] = u;
                wts[pos] = __expf(srow[u] - gmax) * inv;
            }
            pos++;
        }
    }
    if (tid == 0) g_scnt[rowg] = (total < CAP) ? total : CAP;
}

// ---------------- sparse scatter (replaces GEMM2): outcol = sum_k w*cols[u_k] -
__global__ __launch_bounds__(256) void k_scatter() {
    int v = blockIdx.x & 4095;
    int b = blockIdx.x >> 12;
    int rowg = b*LL + v;
    int cnt = g_scnt[rowg];
    const int*   idx = g_sidx + (size_t)rowg * CAP;
    const float* wts = g_sw   + (size_t)rowg * CAP;
    const __half* cols = g_colsF + (size_t)b*LL*EE;
    int tid = threadIdx.x;

    float a0 = 0.f, a1 = 0.f, a2 = 0.f, a3 = 0.f;
    for (int k = 0; k < cnt; k++) {
        int u = idx[k];            // broadcast
        float w = wts[k];
        uint2 pk = *(const uint2*)(cols + (size_t)u*EE + tid*4);
        __half2 h0 = *(__half2*)&pk.x;
        __half2 h1 = *(__half2*)&pk.y;
        float2 f0 = __half22float2(h0);
        float2 f1 = __half22float2(h1);
        a0 += w*f0.x; a1 += w*f0.y; a2 += w*f1.x; a3 += w*f1.y;
    }
    __half2 o0 = __floats2half2_rn(a0, a1);
    __half2 o1 = __floats2half2_rn(a2, a3);
    uint2 pko;
    pko.x = *(uint32_t*)&o0;
    pko.y = *(uint32_t*)&o1;
    *(uint2*)(g_outcolH + (size_t)rowg*EE + tid*4) = pko;
}

// ---------------- overlap-add (transposed conv gather, fp16 in) ---------------
__global__ void k_overlap(float* __restrict__ out) {
    int idx = blockIdx.x * blockDim.x + threadIdx.x;
    if (idx >= BB*CC*HH*WW) return;
    int X = idx & 127, Y = (idx >> 7) & 127, c = (idx >> 14) & 63, b = idx >> 20;
    float acc = 0.f;
    int y0 = (Y + 1) >> 1;
    int x0 = (X + 1) >> 1;
    #pragma unroll
    for (int dy = 0; dy < 2; dy++) {
        int yc = y0 - dy;
        if (yc < 0 || yc >= 64) continue;
        int ki = Y + 1 - 2*yc;
        if (ki < 0 || ki > 3) continue;
        #pragma unroll
        for (int dx = 0; dx < 2; dx++) {
            int xc = x0 - dx;
            if (xc < 0 || xc >= 64) continue;
            int kj = X + 1 - 2*xc;
            if (kj < 0 || kj > 3) continue;
            acc += __half2float(
                g_outcolH[((size_t)b*LL + xc*64 + yc)*EE + c*16 + ki*4 + kj]);
        }
    }
    out[idx] = acc;
}

// ---------------- launch -------------------------------------------------------
extern "C" void kernel_launch(void* const* d_in, const int* in_sizes, int n_in,
                              void* d_out, int out_size) {
    const float* fg   = (const float*)d_in[0];
    const float* bg   = (const float*)d_in[1];
    const float* mask = (const float*)d_in[2];
    float* out = (float*)d_out;

    k_fgT<<<2048, 256>>>(fg);
    k_bgD<<<2048, 256>>>(bg);
    k_sq<<<1024, 256>>>();
    k_normmask<<<32, 256>>>(mask);
    k_cols<<<32768, 256>>>(bg);

    k_gemm1<<<dim3(32, 32, BB), 256>>>();                 // tensor -> bufA
    k_diagp<<<dim3(2, 2, BB*4096), dim3(8, 32)>>>();      // bufA -> bufB (4-wide taps)
    k_softsp<<<BB*4096, 256>>>();                         // bufB -> sparse lists
    k_scatter<<<BB*4096, 256>>>();                        // sparse -> outcolH
    k_overlap<<<8192, 256>>>(out);
}

// round 17
// speedup vs baseline: 1.4257x; 1.0084x over previous
#include <cuda_runtime.h>
#include <cuda_bf16.h>
#include <cuda_fp16.h>
#include <cstdint>
#include <math.h>

// Problem constants
#define BB 2
#define CC 64
#define HH 128
#define WW 128
#define HS 64          // downsampled H=W
#define LL 4096        // HS*HS
#define EE 1024        // CC*16 (4x4 patch)
#define LSQ (4096*4096)
#define CAP 256        // max kept softmax entries per row

// ---------------- scratch (device globals; no allocation allowed) -------------
__device__ float  g_bgD[BB*LL*CC];          // [b][l][c] fp32 (for norms)
__device__ __half g_bgDH[BB*LL*CC];         // fp16 hi
__device__ __half g_bgDL[BB*LL*CC];         // fp16 lo
__device__ __half g_fgTH[BB*CC*LL];         // [b][c][p] fp16 hi
__device__ __half g_fgTL[BB*CC*LL];         // fp16 lo
__device__ float  g_sq[BB*LL];
__device__ float  g_ninv[BB*LL];
__device__ int    g_maskP[BB*LL];           // indexed by permuted a = j*64+i
__device__ __half g_colsF[(size_t)BB*LL*EE];  // cols fp16, [a][e]
__device__ float  g_bufA[(size_t)BB*LSQ];     // 134 MB
__device__ float  g_bufB[(size_t)BB*LSQ];     // 134 MB
__device__ int    g_scnt[BB*LL];              // sparse row counts
__device__ int    g_sidx[(size_t)BB*LL*CAP];  // sparse col indices (8.4 MB)
__device__ float  g_sw  [(size_t)BB*LL*CAP];  // sparse weights (8.4 MB)
__device__ __half g_outcolH[(size_t)BB*LL*EE]; // fp16 outcol, row pp = x*64+y

// ---------------- prep kernels -----------------------------------------------
__global__ void k_fgT(const float* __restrict__ fg) {
    int t = blockIdx.x * blockDim.x + threadIdx.x;
    if (t >= BB*CC*LL) return;
    int p = t & 4095, c = (t >> 12) & 63, b = t >> 18;
    int y = p >> 6, x = p & 63;
    float v = fg[(((size_t)b*CC + c)*HH + 2*y)*WW + 2*x];
    __half h = __float2half(v);
    size_t o = ((size_t)b*CC + c)*LL + p;
    g_fgTH[o] = h;
    g_fgTL[o] = __float2half(v - __half2float(h));
}

__global__ void k_bgD(const float* __restrict__ bg) {
    int t = blockIdx.x * blockDim.x + threadIdx.x;
    if (t >= BB*LL*CC) return;
    int c = t & 63, l = (t >> 6) & 4095, b = t >> 18;
    int i = l >> 6, j = l & 63;
    float v = bg[(((size_t)b*CC + c)*HH + 2*i)*WW + 2*j];
    size_t o = ((size_t)b*LL + l)*CC + c;
    g_bgD[o] = v;
    __half h = __float2half(v);
    g_bgDH[o] = h;
    g_bgDL[o] = __float2half(v - __half2float(h));
}

// per-location sum of squares over channels (one warp per l)
__global__ void k_sq() {
    int gid = blockIdx.x * blockDim.x + threadIdx.x;
    int gw = gid >> 5;
    int lane = gid & 31;
    if (gw >= BB*LL) return;
    const float* row = g_bgD + (size_t)gw * CC;
    float v0 = row[lane], v1 = row[lane + 32];
    float s = v0*v0 + v1*v1;
    #pragma unroll
    for (int o = 16; o; o >>= 1) s += __shfl_xor_sync(0xffffffffu, s, o);
    if (lane == 0) g_sq[gw] = s;
}

// patch norms (3x3 window of sq) and mask flags (written permuted)
__global__ void k_normmask(const float* __restrict__ mask) {
    int t = blockIdx.x * blockDim.x + threadIdx.x;
    if (t >= BB*LL) return;
    int b = t >> 12, l = t & 4095;
    int i = l >> 6, j = l & 63;
    float ss = 0.f, ms = 0.f;
    for (int di = -1; di <= 1; di++) {
        int ii = i + di; if (ii < 0 || ii >= HS) continue;
        for (int dj = -1; dj <= 1; dj++) {
            int jj = j + dj; if (jj < 0 || jj >= HS) continue;
            ss += g_sq[b*LL + ii*HS + jj];
            ms += mask[((size_t)b*HH + 2*ii)*WW + 2*jj];
        }
    }
    g_ninv[t] = 1.f / fmaxf(sqrtf(ss), 1e-3f);
    g_maskP[b*LL + j*HS + i] = (ms == 0.f) ? 1 : 0;
}

// 4x4 stride-2 patches of full-res background, rows permuted: a = j*64+i
__global__ void k_cols(const float* __restrict__ bg) {
    int t = blockIdx.x * blockDim.x + threadIdx.x;
    if (t >= BB*LL*EE) return;
    int e = t & 1023;
    int a = (t >> 10) & 4095;
    int b = t >> 22;
    int j = a >> 6, i = a & 63;
    int c = e >> 4, ki = (e >> 2) & 3, kj = e & 3;
    int Y = 2*i - 1 + ki, X = 2*j - 1 + kj;
    float v = 0.f;
    if (Y >= 0 && Y < HH && X >= 0 && X < WW)
        v = bg[(((size_t)b*CC + c)*HH + Y)*WW + X];
    g_colsF[(size_t)t] = __float2half(v);
}

// ---------------- tensor-core helpers -----------------------------------------
__device__ __forceinline__ void ldsm_x4(uint32_t* r, uint32_t addr) {
    asm volatile("ldmatrix.sync.aligned.m8n8.x4.shared.b16 {%0,%1,%2,%3}, [%4];"
        : "=r"(r[0]), "=r"(r[1]), "=r"(r[2]), "=r"(r[3]) : "r"(addr));
}
__device__ __forceinline__ void ldsm_x4_t(uint32_t* r, uint32_t addr) {
    asm volatile("ldmatrix.sync.aligned.m8n8.x4.trans.shared.b16 {%0,%1,%2,%3}, [%4];"
        : "=r"(r[0]), "=r"(r[1]), "=r"(r[2]), "=r"(r[3]) : "r"(addr));
}
__device__ __forceinline__ void mma_f16(float* c, const uint32_t* a, const uint32_t* b) {
    asm volatile(
        "mma.sync.aligned.m16n8k16.row.col.f32.f16.f16.f32 "
        "{%0,%1,%2,%3}, {%4,%5,%6,%7}, {%8,%9}, {%0,%1,%2,%3};"
        : "+f"(c[0]), "+f"(c[1]), "+f"(c[2]), "+f"(c[3])
        : "r"(a[0]), "r"(a[1]), "r"(a[2]), "r"(a[3]), "r"(b[0]), "r"(b[1]));
}

// ---------------- GEMM1 (tensor): S0[l,p] = sum_c bgD[l,c]*fgT[c,p] -> bufA ---
// fp16 hi/lo both operands, 3 MMAs (ah*bh + ah*bl + al*bh). K=64 in 2 k32 steps.
__global__ __launch_bounds__(256) void k_gemm1() {
    __shared__ __half sAh[128][40], sAl[128][40];
    __shared__ __half sBh[32][136], sBl[32][136];
    int b = blockIdx.z;
    const __half* AH = g_bgDH + (size_t)b*LL*CC;
    const __half* AL = g_bgDL + (size_t)b*LL*CC;
    const __half* BH = g_fgTH + (size_t)b*CC*LL;
    const __half* BL = g_fgTL + (size_t)b*CC*LL;
    float* Cm = g_bufA + (size_t)b*LSQ;

    int m0 = blockIdx.y * 128, n0 = blockIdx.x * 128;
    int tid = threadIdx.x;
    int lane = tid & 31, warp = tid >> 5;
    int wm = warp & 1, wn = warp >> 1;
    int lr = lane & 15, lc = lane >> 4;

    float acc[4][4][4];
    #pragma unroll
    for (int mt = 0; mt < 4; mt++) {
        #pragma unroll
        for (int nt = 0; nt < 4; nt++) {
            #pragma unroll
            for (int q = 0; q < 4; q++) acc[mt][nt][q] = 0.f;
        }
    }

    uint32_t bAh = (uint32_t)__cvta_generic_to_shared(&sAh[0][0]);
    uint32_t bAl = (uint32_t)__cvta_generic_to_shared(&sAl[0][0]);
    uint32_t bBh = (uint32_t)__cvta_generic_to_shared(&sBh[0][0]);
    uint32_t bBl = (uint32_t)__cvta_generic_to_shared(&sBl[0][0]);

    for (int k0 = 0; k0 < 64; k0 += 32) {
        __syncthreads();
        #pragma unroll
        for (int i = 0; i < 2; i++) {
            int cid = tid + i*256;
            int m = cid >> 2, kc = (cid & 3) * 8;
            *(uint4*)&sAh[m][kc] = *(const uint4*)(AH + (size_t)(m0+m)*CC + k0 + kc);
            *(uint4*)&sAl[m][kc] = *(const uint4*)(AL + (size_t)(m0+m)*CC + k0 + kc);
            int kb = cid >> 4, nc = (cid & 15) * 8;
            *(uint4*)&sBh[kb][nc] = *(const uint4*)(BH + (size_t)(k0+kb)*LL + n0 + nc);
            *(uint4*)&sBl[kb][nc] = *(const uint4*)(BL + (size_t)(k0+kb)*LL + n0 + nc);
        }
        __syncthreads();

        #pragma unroll
        for (int kk = 0; kk < 32; kk += 16) {
            uint32_t ah[4][4], al[4][4], bh[4][2], bl[4][2];
            #pragma unroll
            for (int mt = 0; mt < 4; mt++) {
                uint32_t offa = (uint32_t)((wm*64 + mt*16 + lr) * 40 + kk + lc*8) * 2u;
                ldsm_x4(ah[mt], bAh + offa);
                ldsm_x4(al[mt], bAl + offa);
            }
            #pragma unroll
            for (int ntp = 0; ntp < 2; ntp++) {
                uint32_t offb = (uint32_t)((kk + lr) * 136 + wn*32 + ntp*16 + lc*8) * 2u;
                uint32_t rh[4], rl[4];
                ldsm_x4_t(rh, bBh + offb);
                ldsm_x4_t(rl, bBl + offb);
                bh[ntp*2][0] = rh[0]; bh[ntp*2][1] = rh[1];
                bh[ntp*2+1][0] = rh[2]; bh[ntp*2+1][1] = rh[3];
                bl[ntp*2][0] = rl[0]; bl[ntp*2][1] = rl[1];
                bl[ntp*2+1][0] = rl[2]; bl[ntp*2+1][1] = rl[3];
            }
            #pragma unroll
            for (int mt = 0; mt < 4; mt++) {
                #pragma unroll
                for (int nt = 0; nt < 4; nt++) {
                    mma_f16(acc[mt][nt], ah[mt], bh[nt]);
                    mma_f16(acc[mt][nt], ah[mt], bl[nt]);
                    mma_f16(acc[mt][nt], al[mt], bh[nt]);
                }
            }
        }
    }

    int g = lane >> 2, tig = lane & 3;
    #pragma unroll
    for (int mt = 0; mt < 4; mt++) {
        int row0 = m0 + wm*64 + mt*16 + g;
        #pragma unroll
        for (int nt = 0; nt < 4; nt++) {
            int col = n0 + wn*32 + nt*8 + tig*2;
            *(float2*)(Cm + (size_t)row0*LL + col)     = make_float2(acc[mt][nt][0], acc[mt][nt][1]);
            *(float2*)(Cm + (size_t)(row0+8)*LL + col) = make_float2(acc[mt][nt][2], acc[mt][nt][3]);
        }
    }
}

// ---------------- fused 27-tap + permutation: bufA -> bufB (permuted) ---------
// 4-outputs-per-thread, 15-row independent tap loads (R14 form).
__global__ void k_diagp() {
    __shared__ float tile[32][33];
    int z = blockIdx.z;
    int b = z >> 12;
    int jy = z & 4095;
    int j = jy >> 6, y = jy & 63;
    const float* S = g_bufA + (size_t)b*LSQ;
    float* D = g_bufB + (size_t)b*LSQ;
    int i0 = blockIdx.x * 32, x0 = blockIdx.y * 32;

    int tx = threadIdx.x;    // 0..7
    int ty = threadIdx.y;    // 0..31
    int i = i0 + ty;
    int xb = x0 + tx*4;
    int l = i*64 + j;
    int p = y*64 + xb;

    float ts[5][4];
    #pragma unroll
    for (int s = 0; s < 5; s++) {
        #pragma unroll
        for (int t = 0; t < 4; t++) ts[s][t] = 0.f;
    }
    #pragma unroll
    for (int s = -2; s <= 2; s++) {
        #pragma unroll
        for (int di = -1; di <= 1; di++) {
            int dd = s + 64*di;
            int l2 = l + dd;
            if (l2 < 0 || l2 >= LL) continue;
            const float* row = S + (size_t)l2*LL;
            int pb = p + dd;
            #pragma unroll
            for (int t = 0; t < 4; t++) {
                int p2 = pb + t;
                if (p2 >= 0 && p2 < LL) ts[s+2][t] += row[p2];
            }
        }
    }

    float out[4] = {0.f, 0.f, 0.f, 0.f};
    #pragma unroll
    for (int d = -1; d <= 1; d++) {
        int lcn = l + d;
        if (lcn < 0 || lcn >= LL) continue;
        float nv = g_ninv[b*LL + lcn];
        int jc = lcn & 63;
        #pragma unroll
        for (int t = 0; t < 4; t++) {
            int pcn = p + t + d;
            if (pcn < 0 || pcn >= LL) continue;
            int xc = pcn & 63;
            float inner = 0.f;
            #pragma unroll
            for (int dj = -1; dj <= 1; dj++) {
                if (jc + dj < 0 || jc + dj > 63 || xc + dj < 0 || xc + dj > 63) continue;
                inner += ts[d + dj + 2][t];
            }
            out[t] += inner * nv;
        }
    }

    #pragma unroll
    for (int t = 0; t < 4; t++) tile[ty][tx*4 + t] = out[t];
    __syncthreads();

    int wtid = tx + ty*8;
    int il = wtid & 31;
    #pragma unroll
    for (int k = 0; k < 4; k++) {
        int xl = (wtid >> 5) + k*8;
        D[(size_t)((x0 + xl)*64 + y)*LL + j*64 + i0 + il] = tile[il][xl];
    }
}

// ---------------- fuse #2 + mask + sparse softmax (exp only above cutoff) -----
// Entries with val <= gmax-18 contribute <= 4096*e^-18 = 6.2e-5 of the sum;
// they are dropped from BOTH the numerator set and the denominator, so kept
// weights sum to exactly 1. MUFU count drops from 8192/row to ~2*kept.
__global__ __launch_bounds__(256) void k_softsp() {
    __shared__ float srow[4096];
    __shared__ float sred[8];
    __shared__ int   swtot[8];
    __shared__ int   swpre[9];
    int v = blockIdx.x & 4095;
    int b = blockIdx.x >> 12;
    const float* S = g_bufB + (size_t)b*LSQ;
    int rowg = b*LL + v;
    int tid = threadIdx.x;
    int lane = tid & 31, wid = tid >> 5;

    float lmax = -1e30f;
    for (int u = tid; u < 4096; u += 256) {
        float acc = S[(size_t)v*LL + u];
        if (v > 0    && u > 0)    acc += S[(size_t)(v-1)*LL + u - 1];
        if (v < 4095 && u < 4095) acc += S[(size_t)(v+1)*LL + u + 1];
        float val = g_maskP[b*LL + u] ? -1000.f : acc;
        val *= 10.f;
        srow[u] = val;
        lmax = fmaxf(lmax, val);
    }
    #pragma unroll
    for (int o = 16; o; o >>= 1) lmax = fmaxf(lmax, __shfl_xor_sync(0xffffffffu, lmax, o));
    if (lane == 0) sred[wid] = lmax;
    __syncthreads();
    if (tid == 0) {
        float m = sred[0];
        #pragma unroll
        for (int w = 1; w < 8; w++) m = fmaxf(m, sred[w]);
        sred[0] = m;
    }
    __syncthreads();
    float gmax = sred[0];
    float T = gmax - 18.f;
    __syncthreads();

    // count kept entries + denominator over kept only (exp only where needed)
    float lsum = 0.f;
    int cnt = 0;
    for (int u = tid; u < 4096; u += 256) {
        if (srow[u] > T) {
            lsum += __expf(srow[u] - gmax);
            cnt++;
        }
    }
    #pragma unroll
    for (int o = 16; o; o >>= 1) lsum += __shfl_xor_sync(0xffffffffu, lsum, o);
    if (lane == 0) sred[wid] = lsum;
    int incl = cnt;
    #pragma unroll
    for (int o = 1; o < 32; o <<= 1) {
        int n = __shfl_up_sync(0xffffffffu, incl, o);
        if (lane >= o) incl += n;
    }
    if (lane == 31) swtot[wid] = incl;
    __syncthreads();
    if (tid == 0) {
        float s2 = 0.f;
        int s = 0;
        #pragma unroll
        for (int w = 0; w < 8; w++) {
            s2 += sred[w];
            swpre[w] = s; s += swtot[w];
        }
        sred[0] = s2;
        swpre[8] = s;
    }
    __syncthreads();
    float inv = 1.f / sred[0];
    int pos = swpre[wid] + incl - cnt;
    int total = swpre[8];

    int*   idx = g_sidx + (size_t)rowg * CAP;
    float* wts = g_sw   + (size_t)rowg * CAP;
    for (int u = tid; u < 4096; u += 256) {
        if (srow[u] > T) {
            if (pos < CAP) {
                idx[pos] = u;
                wts[pos] = __expf(srow[u] - gmax) * inv;
            }
            pos++;
        }
    }
    if (tid == 0) g_scnt[rowg] = (total < CAP) ? total : CAP;
}

// ---------------- sparse scatter (replaces GEMM2): outcol = sum_k w*cols[u_k] -
__global__ __launch_bounds__(256) void k_scatter() {
    int v = blockIdx.x & 4095;
    int b = blockIdx.x >> 12;
    int rowg = b*LL + v;
    int cnt = g_scnt[rowg];
    const int*   idx = g_sidx + (size_t)rowg * CAP;
    const float* wts = g_sw   + (size_t)rowg * CAP;
    const __half* cols = g_colsF + (size_t)b*LL*EE;
    int tid = threadIdx.x;

    float a0 = 0.f, a1 = 0.f, a2 = 0.f, a3 = 0.f;
    for (int k = 0; k < cnt; k++) {
        int u = idx[k];            // broadcast
        float w = wts[k];
        uint2 pk = *(const uint2*)(cols + (size_t)u*EE + tid*4);
        __half2 h0 = *(__half2*)&pk.x;
        __half2 h1 = *(__half2*)&pk.y;
        float2 f0 = __half22float2(h0);
        float2 f1 = __half22float2(h1);
        a0 += w*f0.x; a1 += w*f0.y; a2 += w*f1.x; a3 += w*f1.y;
    }
    __half2 o0 = __floats2half2_rn(a0, a1);
    __half2 o1 = __floats2half2_rn(a2, a3);
    uint2 pko;
    pko.x = *(uint32_t*)&o0;
    pko.y = *(uint32_t*)&o1;
    *(uint2*)(g_outcolH + (size_t)rowg*EE + tid*4) = pko;
}

// ---------------- overlap-add (transposed conv gather, fp16 in) ---------------
__global__ void k_overlap(float* __restrict__ out) {
    int idx = blockIdx.x * blockDim.x + threadIdx.x;
    if (idx >= BB*CC*HH*WW) return;
    int X = idx & 127, Y = (idx >> 7) & 127, c = (idx >> 14) & 63, b = idx >> 20;
    float acc = 0.f;
    int y0 = (Y + 1) >> 1;
    int x0 = (X + 1) >> 1;
    #pragma unroll
    for (int dy = 0; dy < 2; dy++) {
        int yc = y0 - dy;
        if (yc < 0 || yc >= 64) continue;
        int ki = Y + 1 - 2*yc;
        if (ki < 0 || ki > 3) continue;
        #pragma unroll
        for (int dx = 0; dx < 2; dx++) {
            int xc = x0 - dx;
            if (xc < 0 || xc >= 64) continue;
            int kj = X + 1 - 2*xc;
            if (kj < 0 || kj > 3) continue;
            acc += __half2float(
                g_outcolH[((size_t)b*LL + xc*64 + yc)*EE + c*16 + ki*4 + kj]);
        }
    }
    out[idx] = acc;
}

// ---------------- launch -------------------------------------------------------
extern "C" void kernel_launch(void* const* d_in, const int* in_sizes, int n_in,
                              void* d_out, int out_size) {
    const float* fg   = (const float*)d_in[0];
    const float* bg   = (const float*)d_in[1];
    const float* mask = (const float*)d_in[2];
    float* out = (float*)d_out;

    k_fgT<<<2048, 256>>>(fg);
    k_bgD<<<2048, 256>>>(bg);
    k_sq<<<1024, 256>>>();
    k_normmask<<<32, 256>>>(mask);
    k_cols<<<32768, 256>>>(bg);

    k_gemm1<<<dim3(32, 32, BB), 256>>>();                 // tensor -> bufA
    k_diagp<<<dim3(2, 2, BB*4096), dim3(8, 32)>>>();      // bufA -> bufB (4-wide taps)
    k_softsp<<<BB*4096, 256>>>();                         // bufB -> sparse lists
    k_scatter<<<BB*4096, 256>>>();                        // sparse -> outcolH
    k_overlap<<<8192, 256>>>(out);
}